// round 14
// baseline (speedup 1.0000x reference)
#include <cuda_runtime.h>
#include <cuda_fp16.h>
#include <cstdint>

#define N_NODES   50000
#define N_EDGES_C 1600000
#define TILE_E    384
#define NT        384
#define PC_NODES  128

// Scratch: per-node fp16 [vfeat@W1_recv + 0.5*b1 | vfeat@W1_send + 0.5*b1],
// chunk-major permuted: half index = jc*32 + tg*8 + jj*2 + c  where
// col = 8*(4*jc+jj) + 2*tg + c.  Each (row, jc) chunk is 64 B contiguous.
__device__ __half g_Ph[(size_t)N_NODES * 256];

// ============================ helpers ============================
__device__ __forceinline__ void mma_f16(float* c, const uint32_t* a, uint32_t b0, uint32_t b1) {
    asm volatile("mma.sync.aligned.m16n8k16.row.col.f32.f16.f16.f32 "
        "{%0,%1,%2,%3}, {%4,%5,%6,%7}, {%8,%9}, {%0,%1,%2,%3};"
        : "+f"(c[0]), "+f"(c[1]), "+f"(c[2]), "+f"(c[3])
        : "r"(a[0]), "r"(a[1]), "r"(a[2]), "r"(a[3]), "r"(b0), "r"(b1));
}

__device__ __forceinline__ uint32_t pack_h2(float x, float y) {
    __half2 h = __floats2half2_rn(x, y);
    return *reinterpret_cast<uint32_t*>(&h);
}
__device__ __forceinline__ void wsplit(float w0, float w1, uint32_t& hi, uint32_t& lo) {
    float h0 = __half2float(__float2half_rn(w0));
    float h1 = __half2float(__float2half_rn(w1));
    hi = pack_h2(h0, h1);
    lo = pack_h2(w0 - h0, w1 - h1);
}
__device__ __forceinline__ float2 h2f(uint32_t u) {
    __half2 h = *reinterpret_cast<__half2*>(&u);
    return __half22float2(h);
}

// ---------------------------------------------------------------------------
// HMMA precompute: P[n] = vfeat[n] @ W1cat + 0.5*b1  (both halves),
// 3-term fp16 (vh@Wh + vl@Wh + vh@Wl), stored fp16 chunk-major permuted with
// fully coalesced uint4 stores. 256 threads, 8 warps x 16 nodes = 128 nodes/CTA.
// ---------------------------------------------------------------------------
__global__ void __launch_bounds__(256)
precompute_kernel(const float* __restrict__ vfeat, const float* __restrict__ W1,
                  const float* __restrict__ b1) {
    extern __shared__ char smraw[];
    uint4* wc = (uint4*)smraw;   // [32 J][4 s][32 lane] {b0h,b1h,b0l,b1l}  64 KB

    const int tid = threadIdx.x;
    const int wid = tid >> 5, lid = tid & 31;
    const int gq  = lid >> 2;
    const int tg  = lid & 3;

    // Stage W1cat fragments (hi/lo interleaved)
    for (int idx = tid; idx < 4096; idx += 256) {
        int lane = idx & 31, s = (idx >> 5) & 3, J = idx >> 7;
        int k = 16 * s + 2 * (lane & 3);
        int col = 8 * J + (lane >> 2);
        int r0 = (col < 128) ? (64 + k)  : (128 + k);
        int c0 = (col < 128) ? col : (col - 128);
        uint4 f;
        wsplit(W1[r0 * 128 + c0],       W1[(r0 + 1) * 128 + c0], f.x, f.z);
        wsplit(W1[(r0 + 8) * 128 + c0], W1[(r0 + 9) * 128 + c0], f.y, f.w);
        wc[idx] = f;
    }
    __syncthreads();

    const int n0 = blockIdx.x * PC_NODES + wid * 16 + gq;
    const int n1 = n0 + 8;
    const int n0c = n0 < N_NODES ? n0 : (N_NODES - 1);
    const int n1c = n1 < N_NODES ? n1 : (N_NODES - 1);

    // A fragments from vfeat (fp16 hi/lo)
    uint32_t ah[4][4], al[4][4];
    {
        const float* v0 = vfeat + (size_t)n0c * 64;
        const float* v1 = vfeat + (size_t)n1c * 64;
#pragma unroll
        for (int s = 0; s < 4; s++) {
            int k = 16 * s + 2 * tg;
            float2 x0 = *(const float2*)(v0 + k);
            float2 x1 = *(const float2*)(v1 + k);
            float2 x2 = *(const float2*)(v0 + k + 8);
            float2 x3 = *(const float2*)(v1 + k + 8);
            wsplit(x0.x, x0.y, ah[s][0], al[s][0]);
            wsplit(x1.x, x1.y, ah[s][1], al[s][1]);
            wsplit(x2.x, x2.y, ah[s][2], al[s][2]);
            wsplit(x3.x, x3.y, ah[s][3], al[s][3]);
        }
    }

    // Accumulators init with 0.5*b1, then 3-term mma
    float c[32][4];
#pragma unroll
    for (int J = 0; J < 32; J++) {
        int col = 8 * J + 2 * tg;
        float bb0 = 0.5f * b1[col & 127];
        float bb1 = 0.5f * b1[(col + 1) & 127];
        c[J][0] = bb0; c[J][1] = bb1; c[J][2] = bb0; c[J][3] = bb1;
    }
#pragma unroll
    for (int J = 0; J < 32; J++) {
#pragma unroll
        for (int s = 0; s < 4; s++) {
            uint4 f = wc[(J * 4 + s) * 32 + lid];
            mma_f16(c[J], ah[s], f.x, f.y);
            mma_f16(c[J], al[s], f.x, f.y);
            mma_f16(c[J], ah[s], f.z, f.w);
        }
    }

    // Coalesced permuted stores: per (node, h, jc) a lane-quad writes 64 B.
    char* Pb = (char*)g_Ph;
#pragma unroll
    for (int h = 0; h < 2; h++) {
#pragma unroll
        for (int jc = 0; jc < 4; jc++) {
            uint4 u0, u1;
            uint32_t* p0 = (uint32_t*)&u0;
            uint32_t* p1 = (uint32_t*)&u1;
#pragma unroll
            for (int jj = 0; jj < 4; jj++) {
                int J = h * 16 + 4 * jc + jj;
                p0[jj] = pack_h2(c[J][0], c[J][1]);
                p1[jj] = pack_h2(c[J][2], c[J][3]);
            }
            uint32_t off = (uint32_t)h * 256u + jc * 64u + tg * 16u;
            if (n0 < N_NODES) *(uint4*)(Pb + (size_t)n0 * 512 + off) = u0;
            if (n1 < N_NODES) *(uint4*)(Pb + (size_t)n1 * 512 + off) = u1;
        }
    }
}

// ---------------------------------------------------------------------------
// Persistent HMMA edge kernel. fp16 single-term weights, fp16 activations.
// 384 threads (12 warps)/CTA, M=32 rows/warp, TILE_E=384.
// 12 warps/SM = 3/SMSP (even) with M=32 weight-LDS amortization.
// ---------------------------------------------------------------------------
__global__ void __launch_bounds__(NT, 1)
edge_kernel(const float* __restrict__ edata,
            const float* __restrict__ W1,
            const float* __restrict__ W2,
            const float* __restrict__ b2,
            const void*  __restrict__ senders,
            const void*  __restrict__ receivers,
            float* __restrict__ out) {
    extern __shared__ char smraw[];
    uint2* w1h = (uint2*)smraw;              // [16 J][4 s][32 lane] hi   16 KB
    uint2* w2h = (uint2*)(w1h + 2048);       // [8 j][8 t][32 lane] hi    16 KB
    float* b2f = (float*)(w2h + 2048);       // 64
    int*   sFlag = (int*)(b2f + 64);

    const int tid = threadIdx.x;
    const int wid = tid >> 5, lid = tid & 31;
    const int gq  = lid >> 2;     // fragment row
    const int tg  = lid & 3;      // fragment col pair

    if (tid < 32) {
        unsigned hiw = ((const unsigned*)senders)[2 * tid + 1];
        unsigned ball = __ballot_sync(0xffffffffu, hiw == 0u);
        if (tid == 0) *sFlag = (ball == 0xffffffffu);
    }

    // ---- Stage W1 fragments (fp16 hi only)
    for (int idx = tid; idx < 2048; idx += NT) {
        int lane = idx & 31, s = (idx >> 5) & 3, j = idx >> 7;
        int k = 16 * s + 2 * (lane & 3);
        int n = 8 * j + (lane >> 2);
        uint2 f;
        f.x = pack_h2(W1[k * 128 + n],       W1[(k + 1) * 128 + n]);
        f.y = pack_h2(W1[(k + 8) * 128 + n], W1[(k + 9) * 128 + n]);
        w1h[idx] = f;
    }
    // ---- Stage W2 fragments (fp16 hi only)
    for (int idx = tid; idx < 2048; idx += NT) {
        int lane = idx & 31, t = (idx >> 5) & 7, j = idx >> 8;
        int k = 16 * t + 2 * (lane & 3);
        int n = 8 * j + (lane >> 2);
        uint2 f;
        f.x = pack_h2(W2[k * 64 + n],       W2[(k + 1) * 64 + n]);
        f.y = pack_h2(W2[(k + 8) * 64 + n], W2[(k + 9) * 64 + n]);
        w2h[idx] = f;
    }
    if (tid < 64) b2f[tid] = b2[tid];
    __syncthreads();

    const int idx64 = *sFlag;
    const long long* r64 = (const long long*)receivers;
    const int*       r32 = (const int*)receivers;
    const long long* s64 = (const long long*)senders;
    const int*       s32 = (const int*)senders;

    const char* Pbase = (const char*)g_Ph;
    const int ntiles = (N_EDGES_C + TILE_E - 1) / TILE_E;   // 4167 (last partial)

    for (int tile = blockIdx.x; tile < ntiles; tile += gridDim.x) {
        const int base = tile * TILE_E + wid * 32 + gq;
        int em[4];
        em[0] = base;      em[1] = base + 8;
        em[2] = base + 16; em[3] = base + 24;

        uint32_t offR[4], offS[4];
#pragma unroll
        for (int q = 0; q < 4; q++) {
            int e = em[q] < N_EDGES_C ? em[q] : (N_EDGES_C - 1);
            int rr = idx64 ? (int)r64[e] : r32[e];
            int ss = idx64 ? (int)s64[e] : s32[e];
            offR[q] = (uint32_t)rr * 512u + tg * 16u;
            offS[q] = (uint32_t)ss * 512u + 256u + tg * 16u;
        }

        // ---- A1 fragments from edata (fp16 quantize)
        uint32_t a1[2][4][4];
#pragma unroll
        for (int b = 0; b < 2; b++) {
            int e0 = em[2 * b] < N_EDGES_C ? em[2 * b] : (N_EDGES_C - 1);
            int e1 = em[2 * b + 1] < N_EDGES_C ? em[2 * b + 1] : (N_EDGES_C - 1);
            const float* x0 = edata + (size_t)e0 * 64;
            const float* x1 = edata + (size_t)e1 * 64;
#pragma unroll
            for (int s = 0; s < 4; s++) {
                int k = 16 * s + 2 * tg;
                float2 v0 = *(const float2*)(x0 + k);
                float2 v1 = *(const float2*)(x1 + k);
                float2 v2 = *(const float2*)(x0 + k + 8);
                float2 v3 = *(const float2*)(x1 + k + 8);
                a1[b][s][0] = pack_h2(v0.x, v0.y);
                a1[b][s][1] = pack_h2(v1.x, v1.y);
                a1[b][s][2] = pack_h2(v2.x, v2.y);
                a1[b][s][3] = pack_h2(v3.x, v3.y);
            }
        }

        // ---- GEMM1 in 4 chunks of 4 J; produce fp16 A2 fragments
        uint32_t a2[2][8][4];
#pragma unroll
        for (int jc = 0; jc < 4; jc++) {
            float c1[2][4][4];
#pragma unroll
            for (int b = 0; b < 2; b++) {
                uint4 ra = *(const uint4*)(Pbase + offR[2 * b]     + jc * 64);
                uint4 sa = *(const uint4*)(Pbase + offS[2 * b]     + jc * 64);
                uint4 rb = *(const uint4*)(Pbase + offR[2 * b + 1] + jc * 64);
                uint4 sb = *(const uint4*)(Pbase + offS[2 * b + 1] + jc * 64);
                const uint32_t* raw = (const uint32_t*)&ra;
                const uint32_t* saw = (const uint32_t*)&sa;
                const uint32_t* rbw = (const uint32_t*)&rb;
                const uint32_t* sbw = (const uint32_t*)&sb;
#pragma unroll
                for (int jj = 0; jj < 4; jj++) {
                    float2 fa = h2f(raw[jj]), fb = h2f(saw[jj]);
                    float2 fc = h2f(rbw[jj]), fd = h2f(sbw[jj]);
                    c1[b][jj][0] = fa.x + fb.x;
                    c1[b][jj][1] = fa.y + fb.y;
                    c1[b][jj][2] = fc.x + fd.x;
                    c1[b][jj][3] = fc.y + fd.y;
                }
            }
#pragma unroll
            for (int jj = 0; jj < 4; jj++) {
                int J = 4 * jc + jj;
#pragma unroll
                for (int s = 0; s < 4; s++) {
                    uint2 f = w1h[(J * 4 + s) * 32 + lid];
#pragma unroll
                    for (int b = 0; b < 2; b++)
                        mma_f16(c1[b][jj], a1[b][s], f.x, f.y);
                }
            }
            // relu + fp16 pack into A2 frags (t = 2jc, 2jc+1)
#pragma unroll
            for (int b = 0; b < 2; b++) {
#pragma unroll
                for (int p = 0; p < 2; p++) {
                    int t = 2 * jc + p;
                    a2[b][t][0] = pack_h2(fmaxf(c1[b][2 * p][0], 0.0f),     fmaxf(c1[b][2 * p][1], 0.0f));
                    a2[b][t][1] = pack_h2(fmaxf(c1[b][2 * p][2], 0.0f),     fmaxf(c1[b][2 * p][3], 0.0f));
                    a2[b][t][2] = pack_h2(fmaxf(c1[b][2 * p + 1][0], 0.0f), fmaxf(c1[b][2 * p + 1][1], 0.0f));
                    a2[b][t][3] = pack_h2(fmaxf(c1[b][2 * p + 1][2], 0.0f), fmaxf(c1[b][2 * p + 1][3], 0.0f));
                }
            }
        }

        // ---- GEMM2 (single-term) in 2 halves of 4 j, stores interleaved
#pragma unroll
        for (int jh = 0; jh < 2; jh++) {
            float d2[2][4][4];
#pragma unroll
            for (int jj = 0; jj < 4; jj++) {
                int j = 4 * jh + jj;
                float2 bb = *(const float2*)(b2f + 8 * j + 2 * tg);
#pragma unroll
                for (int b = 0; b < 2; b++) {
                    d2[b][jj][0] = bb.x; d2[b][jj][1] = bb.y;
                    d2[b][jj][2] = bb.x; d2[b][jj][3] = bb.y;
                }
            }
#pragma unroll
            for (int jj = 0; jj < 4; jj++) {
                int j = 4 * jh + jj;
#pragma unroll
                for (int t = 0; t < 8; t++) {
                    uint2 f = w2h[(j * 8 + t) * 32 + lid];
#pragma unroll
                    for (int b = 0; b < 2; b++)
                        mma_f16(d2[b][jj], a2[b][t], f.x, f.y);
                }
            }
#pragma unroll
            for (int b = 0; b < 2; b++) {
                if (em[2 * b] < N_EDGES_C) {
                    float* o0 = out + (size_t)em[2 * b] * 64 + 32 * jh;
#pragma unroll
                    for (int jj = 0; jj < 4; jj++)
                        *(float2*)(o0 + 8 * jj + 2 * tg) = make_float2(d2[b][jj][0], d2[b][jj][1]);
                }
                if (em[2 * b + 1] < N_EDGES_C) {
                    float* o1 = out + (size_t)em[2 * b + 1] * 64 + 32 * jh;
#pragma unroll
                    for (int jj = 0; jj < 4; jj++)
                        *(float2*)(o1 + 8 * jj + 2 * tg) = make_float2(d2[b][jj][2], d2[b][jj][3]);
                }
            }
        }
    }
}

// ---------------------------------------------------------------------------
extern "C" void kernel_launch(void* const* d_in, const int* in_sizes, int n_in,
                              void* d_out, int out_size) {
    const float* edata     = (const float*)d_in[0];
    const float* vfeat     = (const float*)d_in[1];
    const float* W1        = (const float*)d_in[2];
    const float* b1        = (const float*)d_in[3];
    const float* W2        = (const float*)d_in[4];
    const float* b2        = (const float*)d_in[5];
    const void*  senders   = d_in[6];
    const void*  receivers = d_in[7];
    float* out = (float*)d_out;
    (void)in_sizes; (void)n_in; (void)out_size;

    const int pc_smem = 4096 * 16;                                  // 65536 B
    const int e_smem  = 2048 * 8 * 2 + 64 * 4 + 16;                 // 33040 B

    cudaFuncSetAttribute(precompute_kernel,
                         cudaFuncAttributeMaxDynamicSharedMemorySize, pc_smem);
    cudaFuncSetAttribute(edge_kernel,
                         cudaFuncAttributeMaxDynamicSharedMemorySize, e_smem);

    int sms = 0;
    cudaDeviceGetAttribute(&sms, cudaDevAttrMultiProcessorCount, 0);
    if (sms <= 0) sms = 148;

    precompute_kernel<<<(N_NODES + PC_NODES - 1) / PC_NODES, 256, pc_smem>>>(vfeat, W1, b1);
    edge_kernel<<<sms, NT, e_smem>>>(edata, W1, W2, b2, senders, receivers, out);
}

// round 15
// speedup vs baseline: 1.0296x; 1.0296x over previous
#include <cuda_runtime.h>
#include <cuda_fp16.h>
#include <cstdint>

#define N_NODES   50000
#define N_EDGES_C 1600000
#define TILE_E    256
#define NT        512

// Scratch: per-node fp16 [vfeat@W1_recv + 0.5*b1 | vfeat@W1_send + 0.5*b1],
// chunk-major permuted: half index = jc*32 + tg*8 + jj*2 + c  where
// col = 8*(4*jc+jj) + 2*tg + c.  Each (row, jc) chunk is 64 B contiguous.
__device__ __half g_Ph[(size_t)N_NODES * 256];
__device__ unsigned int g_bar;   // monotone ticket barrier (replay-safe)

// ============================ helpers ============================
__device__ __forceinline__ void mma_f16(float* c, const uint32_t* a, uint32_t b0, uint32_t b1) {
    asm volatile("mma.sync.aligned.m16n8k16.row.col.f32.f16.f16.f32 "
        "{%0,%1,%2,%3}, {%4,%5,%6,%7}, {%8,%9}, {%0,%1,%2,%3};"
        : "+f"(c[0]), "+f"(c[1]), "+f"(c[2]), "+f"(c[3])
        : "r"(a[0]), "r"(a[1]), "r"(a[2]), "r"(a[3]), "r"(b0), "r"(b1));
}

__device__ __forceinline__ uint32_t pack_h2(float x, float y) {
    __half2 h = __floats2half2_rn(x, y);
    return *reinterpret_cast<uint32_t*>(&h);
}
__device__ __forceinline__ void wsplit(float w0, float w1, uint32_t& hi, uint32_t& lo) {
    float h0 = __half2float(__float2half_rn(w0));
    float h1 = __half2float(__float2half_rn(w1));
    hi = pack_h2(h0, h1);
    lo = pack_h2(w0 - h0, w1 - h1);
}
__device__ __forceinline__ float2 h2f(uint32_t u) {
    __half2 h = *reinterpret_cast<__half2*>(&u);
    return __half22float2(h);
}

// ---------------------------------------------------------------------------
// Fused persistent kernel.
//  Phase 1: P[n] = vfeat[n] @ W1cat + 0.5*b1 (both halves), HMMA 3-term fp16,
//           stored fp16 chunk-major permuted (coalesced uint4 stores).
//  Device-wide ticket barrier (all CTAs co-resident: grid = #SMs).
//  Phase 2: edge MLP, fp16 single-term weights, fp16 activations,
//           M=16 rows/warp, 16 warps/CTA (proven R13 config).
// ---------------------------------------------------------------------------
__global__ void __launch_bounds__(NT, 1)
fused_kernel(const float* __restrict__ edata,
             const float* __restrict__ vfeat,
             const float* __restrict__ W1,
             const float* __restrict__ b1,
             const float* __restrict__ W2,
             const float* __restrict__ b2,
             const void*  __restrict__ senders,
             const void*  __restrict__ receivers,
             float* __restrict__ out) {
    extern __shared__ char smraw[];
    // Phase 1 view: wc = [32 J][4 s][32 lane] uint4 (64 KB)
    uint4* wc = (uint4*)smraw;
    // Phase 2 view (aliases first 32 KB): w1h, w2h
    uint2* w1h = (uint2*)smraw;              // 16 KB
    uint2* w2h = (uint2*)(w1h + 2048);       // 16 KB
    float* b2f = (float*)(smraw + 65536);    // 64 floats
    int*   sFlag = (int*)(b2f + 64);

    const int tid = threadIdx.x;
    const int wid = tid >> 5, lid = tid & 31;
    const int gq  = lid >> 2;
    const int tg  = lid & 3;

    // =================== Phase 1: precompute P ===================
    // Stage W1cat fragments (hi/lo interleaved)
    for (int idx = tid; idx < 4096; idx += NT) {
        int lane = idx & 31, s = (idx >> 5) & 3, J = idx >> 7;
        int k = 16 * s + 2 * (lane & 3);
        int col = 8 * J + (lane >> 2);
        int r0 = (col < 128) ? (64 + k)  : (128 + k);
        int c0 = (col < 128) ? col : (col - 128);
        uint4 f;
        wsplit(W1[r0 * 128 + c0],       W1[(r0 + 1) * 128 + c0], f.x, f.z);
        wsplit(W1[(r0 + 8) * 128 + c0], W1[(r0 + 9) * 128 + c0], f.y, f.w);
        wc[idx] = f;
    }
    __syncthreads();

    {
        char* Pb = (char*)g_Ph;
        const int NB = (N_NODES + 255) / 256;   // 256 nodes per CTA-iter (16 warps x 16)
        for (int nb = blockIdx.x; nb < NB; nb += gridDim.x) {
            const int n0 = nb * 256 + wid * 16 + gq;
            const int n1 = n0 + 8;
            const int n0c = n0 < N_NODES ? n0 : (N_NODES - 1);
            const int n1c = n1 < N_NODES ? n1 : (N_NODES - 1);

            // A fragments from vfeat (fp16 hi/lo)
            uint32_t ah[4][4], al[4][4];
            {
                const float* v0 = vfeat + (size_t)n0c * 64;
                const float* v1 = vfeat + (size_t)n1c * 64;
#pragma unroll
                for (int s = 0; s < 4; s++) {
                    int k = 16 * s + 2 * tg;
                    float2 x0 = *(const float2*)(v0 + k);
                    float2 x1 = *(const float2*)(v1 + k);
                    float2 x2 = *(const float2*)(v0 + k + 8);
                    float2 x3 = *(const float2*)(v1 + k + 8);
                    wsplit(x0.x, x0.y, ah[s][0], al[s][0]);
                    wsplit(x1.x, x1.y, ah[s][1], al[s][1]);
                    wsplit(x2.x, x2.y, ah[s][2], al[s][2]);
                    wsplit(x3.x, x3.y, ah[s][3], al[s][3]);
                }
            }

            // Process the two 128-col halves sequentially (bounds live regs)
#pragma unroll
            for (int h = 0; h < 2; h++) {
                float c[16][4];
#pragma unroll
                for (int J = 0; J < 16; J++) {
                    int col = 8 * (h * 16 + J) + 2 * tg;
                    float bb0 = 0.5f * b1[col & 127];
                    float bb1 = 0.5f * b1[(col + 1) & 127];
                    c[J][0] = bb0; c[J][1] = bb1; c[J][2] = bb0; c[J][3] = bb1;
                }
#pragma unroll
                for (int J = 0; J < 16; J++) {
#pragma unroll
                    for (int s = 0; s < 4; s++) {
                        uint4 f = wc[((h * 16 + J) * 4 + s) * 32 + lid];
                        mma_f16(c[J], ah[s], f.x, f.y);
                        mma_f16(c[J], al[s], f.x, f.y);
                        mma_f16(c[J], ah[s], f.z, f.w);
                    }
                }
                // Coalesced permuted stores: per (node, h, jc) lane-quad = 64 B.
#pragma unroll
                for (int jc = 0; jc < 4; jc++) {
                    uint4 u0, u1;
                    uint32_t* p0 = (uint32_t*)&u0;
                    uint32_t* p1 = (uint32_t*)&u1;
#pragma unroll
                    for (int jj = 0; jj < 4; jj++) {
                        int J = 4 * jc + jj;
                        p0[jj] = pack_h2(c[J][0], c[J][1]);
                        p1[jj] = pack_h2(c[J][2], c[J][3]);
                    }
                    uint32_t off = (uint32_t)h * 256u + jc * 64u + tg * 16u;
                    if (n0 < N_NODES) *(uint4*)(Pb + (size_t)n0 * 512 + off) = u0;
                    if (n1 < N_NODES) *(uint4*)(Pb + (size_t)n1 * 512 + off) = u1;
                }
            }
        }
    }

    // =================== Device-wide barrier ===================
    __syncthreads();          // CTA done with phase-1 (incl. smem wc reads)
    __threadfence();          // make P stores visible device-wide
    if (tid == 0) {
        unsigned int ticket = atomicAdd(&g_bar, 1u);
        unsigned int target = (ticket / (unsigned)gridDim.x + 1u) * (unsigned)gridDim.x;
        while (atomicAdd(&g_bar, 0u) < target) { }
    }
    __syncthreads();

    // =================== Phase 2: edge MLP ===================
    if (tid < 32) {
        unsigned hiw = ((const unsigned*)senders)[2 * tid + 1];
        unsigned ball = __ballot_sync(0xffffffffu, hiw == 0u);
        if (tid == 0) *sFlag = (ball == 0xffffffffu);
    }

    // Stage W1 fragments (fp16 hi only)
    for (int idx = tid; idx < 2048; idx += NT) {
        int lane = idx & 31, s = (idx >> 5) & 3, j = idx >> 7;
        int k = 16 * s + 2 * (lane & 3);
        int n = 8 * j + (lane >> 2);
        uint2 f;
        f.x = pack_h2(W1[k * 128 + n],       W1[(k + 1) * 128 + n]);
        f.y = pack_h2(W1[(k + 8) * 128 + n], W1[(k + 9) * 128 + n]);
        w1h[idx] = f;
    }
    // Stage W2 fragments (fp16 hi only)
    for (int idx = tid; idx < 2048; idx += NT) {
        int lane = idx & 31, t = (idx >> 5) & 7, j = idx >> 8;
        int k = 16 * t + 2 * (lane & 3);
        int n = 8 * j + (lane >> 2);
        uint2 f;
        f.x = pack_h2(W2[k * 64 + n],       W2[(k + 1) * 64 + n]);
        f.y = pack_h2(W2[(k + 8) * 64 + n], W2[(k + 9) * 64 + n]);
        w2h[idx] = f;
    }
    if (tid < 64) b2f[tid] = b2[tid];
    __syncthreads();

    const int idx64 = *sFlag;
    const long long* r64 = (const long long*)receivers;
    const int*       r32 = (const int*)receivers;
    const long long* s64 = (const long long*)senders;
    const int*       s32 = (const int*)senders;

    const char* Pbase = (const char*)g_Ph;
    const int ntiles = (N_EDGES_C + TILE_E - 1) / TILE_E;   // 6250 exact

    for (int tile = blockIdx.x; tile < ntiles; tile += gridDim.x) {
        const int base = tile * TILE_E + wid * 16 + gq;
        const int em0 = base, em1 = base + 8;
        const int e0c = em0 < N_EDGES_C ? em0 : (N_EDGES_C - 1);
        const int e1c = em1 < N_EDGES_C ? em1 : (N_EDGES_C - 1);

        uint32_t offR0, offS0, offR1, offS1;
        {
            int rr0 = idx64 ? (int)r64[e0c] : r32[e0c];
            int ss0 = idx64 ? (int)s64[e0c] : s32[e0c];
            int rr1 = idx64 ? (int)r64[e1c] : r32[e1c];
            int ss1 = idx64 ? (int)s64[e1c] : s32[e1c];
            offR0 = (uint32_t)rr0 * 512u + tg * 16u;
            offS0 = (uint32_t)ss0 * 512u + 256u + tg * 16u;
            offR1 = (uint32_t)rr1 * 512u + tg * 16u;
            offS1 = (uint32_t)ss1 * 512u + 256u + tg * 16u;
        }

        // A1 fragments from edata (fp16 quantize)
        uint32_t a1[4][4];
        {
            const float* x0 = edata + (size_t)e0c * 64;
            const float* x1 = edata + (size_t)e1c * 64;
#pragma unroll
            for (int s = 0; s < 4; s++) {
                int k = 16 * s + 2 * tg;
                float2 v0 = *(const float2*)(x0 + k);
                float2 v1 = *(const float2*)(x1 + k);
                float2 v2 = *(const float2*)(x0 + k + 8);
                float2 v3 = *(const float2*)(x1 + k + 8);
                a1[s][0] = pack_h2(v0.x, v0.y);
                a1[s][1] = pack_h2(v1.x, v1.y);
                a1[s][2] = pack_h2(v2.x, v2.y);
                a1[s][3] = pack_h2(v3.x, v3.y);
            }
        }

        // GEMM1 in 4 chunks of 4 J; produce fp16 A2 fragments
        uint32_t a2[8][4];
#pragma unroll
        for (int jc = 0; jc < 4; jc++) {
            float c1[4][4];
            {
                uint4 ra = *(const uint4*)(Pbase + offR0 + jc * 64);
                uint4 sa = *(const uint4*)(Pbase + offS0 + jc * 64);
                uint4 rb = *(const uint4*)(Pbase + offR1 + jc * 64);
                uint4 sb = *(const uint4*)(Pbase + offS1 + jc * 64);
                const uint32_t* raw = (const uint32_t*)&ra;
                const uint32_t* saw = (const uint32_t*)&sa;
                const uint32_t* rbw = (const uint32_t*)&rb;
                const uint32_t* sbw = (const uint32_t*)&sb;
#pragma unroll
                for (int jj = 0; jj < 4; jj++) {
                    float2 fa = h2f(raw[jj]), fb = h2f(saw[jj]);
                    float2 fc = h2f(rbw[jj]), fd = h2f(sbw[jj]);
                    c1[jj][0] = fa.x + fb.x;
                    c1[jj][1] = fa.y + fb.y;
                    c1[jj][2] = fc.x + fd.x;
                    c1[jj][3] = fc.y + fd.y;
                }
            }
#pragma unroll
            for (int jj = 0; jj < 4; jj++) {
                int J = 4 * jc + jj;
#pragma unroll
                for (int s = 0; s < 4; s++) {
                    uint2 f = w1h[(J * 4 + s) * 32 + lid];
                    mma_f16(c1[jj], a1[s], f.x, f.y);
                }
            }
#pragma unroll
            for (int p = 0; p < 2; p++) {
                int t = 2 * jc + p;
                a2[t][0] = pack_h2(fmaxf(c1[2 * p][0], 0.0f),     fmaxf(c1[2 * p][1], 0.0f));
                a2[t][1] = pack_h2(fmaxf(c1[2 * p][2], 0.0f),     fmaxf(c1[2 * p][3], 0.0f));
                a2[t][2] = pack_h2(fmaxf(c1[2 * p + 1][0], 0.0f), fmaxf(c1[2 * p + 1][1], 0.0f));
                a2[t][3] = pack_h2(fmaxf(c1[2 * p + 1][2], 0.0f), fmaxf(c1[2 * p + 1][3], 0.0f));
            }
        }

        // GEMM2 (single-term) in 2 halves of 4 j, stores interleaved
#pragma unroll
        for (int jh = 0; jh < 2; jh++) {
            float d2[4][4];
#pragma unroll
            for (int jj = 0; jj < 4; jj++) {
                int j = 4 * jh + jj;
                float2 bb = *(const float2*)(b2f + 8 * j + 2 * tg);
                d2[jj][0] = bb.x; d2[jj][1] = bb.y;
                d2[jj][2] = bb.x; d2[jj][3] = bb.y;
            }
#pragma unroll
            for (int jj = 0; jj < 4; jj++) {
                int j = 4 * jh + jj;
#pragma unroll
                for (int t = 0; t < 8; t++) {
                    uint2 f = w2h[(j * 8 + t) * 32 + lid];
                    mma_f16(d2[jj], a2[t], f.x, f.y);
                }
            }
            if (em0 < N_EDGES_C) {
                float* o0 = out + (size_t)em0 * 64 + 32 * jh;
#pragma unroll
                for (int jj = 0; jj < 4; jj++)
                    *(float2*)(o0 + 8 * jj + 2 * tg) = make_float2(d2[jj][0], d2[jj][1]);
            }
            if (em1 < N_EDGES_C) {
                float* o1 = out + (size_t)em1 * 64 + 32 * jh;
#pragma unroll
                for (int jj = 0; jj < 4; jj++)
                    *(float2*)(o1 + 8 * jj + 2 * tg) = make_float2(d2[jj][2], d2[jj][3]);
            }
        }
    }
}

// ---------------------------------------------------------------------------
extern "C" void kernel_launch(void* const* d_in, const int* in_sizes, int n_in,
                              void* d_out, int out_size) {
    const float* edata     = (const float*)d_in[0];
    const float* vfeat     = (const float*)d_in[1];
    const float* W1        = (const float*)d_in[2];
    const float* b1        = (const float*)d_in[3];
    const float* W2        = (const float*)d_in[4];
    const float* b2        = (const float*)d_in[5];
    const void*  senders   = d_in[6];
    const void*  receivers = d_in[7];
    float* out = (float*)d_out;
    (void)in_sizes; (void)n_in; (void)out_size;

    const int f_smem = 65536 + 64 * 4 + 16;   // 65808 B

    cudaFuncSetAttribute(fused_kernel,
                         cudaFuncAttributeMaxDynamicSharedMemorySize, f_smem);

    int sms = 0;
    cudaDeviceGetAttribute(&sms, cudaDevAttrMultiProcessorCount, 0);
    if (sms <= 0) sms = 148;

    fused_kernel<<<sms, NT, f_smem>>>(edata, vfeat, W1, b1, W2, b2,
                                      senders, receivers, out);
}